// round 1
// baseline (speedup 1.0000x reference)
#include <cuda_runtime.h>
#include <math.h>

#define Bb 16
#define Nn 64
#define Cc 80
#define Hh 128
#define Ww 128
#define HW (Hh*Ww)
#define NB (Bb*Nn)
#define RMAX 16
#define WIN 33
#define WIN2 (WIN*WIN)
#define EPS32 1.1920929e-07f
#define TOTAL (Bb*Cc*HW)

// Persistent scratch. g_ct and g_win maintain a "all zeros between launches"
// invariant: they are zero-initialized at module load, and every launch
// restores zeros via atomicExch / atomicCAS cleanup in the consuming pass.
__device__ int   g_cxi[NB], g_cyi[NB], g_rad[NB], g_cls[NB];
__device__ float g_sig2[NB], g_fx[NB], g_fy[NB], g_sw[NB], g_sh[NB];
__device__ int   g_win[Bb*HW];
__device__ float g_ct[TOTAL];
__device__ double g_acc_c, g_acc_wh, g_acc_of;
__device__ int   g_af;

// ---------------------------------------------------------------------------
__device__ __forceinline__ float block_reduce(float v) {
    __shared__ float sh[32];
    int lane = threadIdx.x & 31;
    int wid  = threadIdx.x >> 5;
    #pragma unroll
    for (int o = 16; o > 0; o >>= 1) v += __shfl_down_sync(0xffffffffu, v, o);
    if (lane == 0) sh[wid] = v;
    __syncthreads();
    int nw = (blockDim.x + 31) >> 5;
    v = (threadIdx.x < nw) ? sh[threadIdx.x] : 0.0f;
    if (wid == 0) {
        #pragma unroll
        for (int o = 16; o > 0; o >>= 1) v += __shfl_down_sync(0xffffffffu, v, o);
    }
    return v;  // valid on thread 0
}

__device__ __forceinline__ float f_bg(float p) {
    // -log(1 - p + 1e-12) * p^2
    return -__logf(1.0f - p + 1e-12f) * (p * p);
}

// ---------------------------------------------------------------------------
// K1: per-box params + per-batch sequential (last-wins) center winner map +
//     accumulator reset.
__global__ void k_init(const float* __restrict__ boxes,
                       const int*  __restrict__ labels) {
    int t = threadIdx.x;          // 0..1023 == (b*64 + n)
    if (t == 0) { g_acc_c = 0.0; g_acc_wh = 0.0; g_acc_of = 0.0; g_af = 0; }

    float x1 = boxes[4*t+0], y1 = boxes[4*t+1];
    float x2 = boxes[4*t+2], y2 = boxes[4*t+3];
    const float wr = 0.25f, hr = 0.25f;            // W/512, H/512
    float cx = ((x1 + x2) * wr) * 0.5f;
    float cy = ((y1 + y2) * hr) * 0.5f;
    int cxi = (int)floorf(cx);
    int cyi = (int)floorf(cy);
    float sw = (x2 - x1) * wr;
    float sh = (y2 - y1) * hr;

    // gaussian radius, mirroring reference fp32 op order
    float h = sh, w = sw;
    float b1 = h + w;
    float c1 = ((w * h) * 0.7f) / 1.3f;
    float sq1 = sqrtf(b1*b1 - 4.0f*c1);
    float r1 = (b1 - sq1) * 0.5f;
    float b2 = 2.0f * (h + w);
    float c2 = (0.7f * w) * h;
    float sq2 = sqrtf(b2*b2 - 16.0f*c2);
    float r2 = (b2 - sq2) * 0.125f;
    float b3 = -0.6f * (h + w);
    float c3 = (-0.7f * w) * h;
    float sq3 = sqrtf(b3*b3 - 4.8f*c3);
    float r3 = (b3 + sq3) / 2.4f;
    float rm = fminf(fminf(r1, r2), r3);
    int rad = (int)fmaxf(0.0f, floorf(rm));

    float d = (float)(2*rad + 1);
    float sig2 = ((2.0f * d) / 6.0f) * (d / 6.0f);

    g_cxi[t] = cxi; g_cyi[t] = cyi; g_rad[t] = rad; g_cls[t] = labels[t];
    g_sig2[t] = sig2;
    g_fx[t] = cx - (float)cxi;  g_fy[t] = cy - (float)cyi;
    g_sw[t] = sw;               g_sh[t] = sh;

    __syncthreads();
    // sequential per-batch writes => last-wins semantics identical to jnp set
    if (t < Bb) {
        for (int n = 0; n < Nn; n++) {
            int i = t * Nn + n;
            g_win[t * HW + g_cyi[i] * Ww + g_cxi[i]] = n + 1;
        }
    }
}

// ---------------------------------------------------------------------------
// K2: scatter-max gaussian kernels into g_ct
__global__ void k_scatter() {
    int id = blockIdx.x * blockDim.x + threadIdx.x;
    if (id >= NB * WIN2) return;
    int box = id / WIN2;
    int r   = id - box * WIN2;
    int dy  = r / WIN - RMAX;
    int dx  = (r % WIN) - RMAX;
    int rad = g_rad[box];
    if (dx > rad || dx < -rad || dy > rad || dy < -rad) return;
    int y = g_cyi[box] + dy;
    int x = g_cxi[box] + dx;
    if ((unsigned)y >= (unsigned)Hh || (unsigned)x >= (unsigned)Ww) return;
    float d2   = (float)(dx*dx + dy*dy);
    float kern = expf(-d2 / g_sig2[box]);
    if (kern < EPS32) return;                    // reference eps threshold
    int b = box >> 6;
    int idx = ((b * Cc + g_cls[box]) * Hh + y) * Ww + x;
    atomicMax((int*)&g_ct[idx], __float_as_int(kern));  // kern > 0: int cmp ok
}

// ---------------------------------------------------------------------------
// K3: dense background focal term over all 21M pixels (memory-bound, vec4)
__global__ void k_bg(const float4* __restrict__ p, int n4) {
    float s = 0.0f;
    for (int i = blockIdx.x * blockDim.x + threadIdx.x; i < n4;
         i += gridDim.x * blockDim.x) {
        float4 v = p[i];
        s += f_bg(v.x) + f_bg(v.y) + f_bg(v.z) + f_bg(v.w);
    }
    float bs = block_reduce(s);
    if (threadIdx.x == 0) atomicAdd(&g_acc_c, (double)bs);
}

// ---------------------------------------------------------------------------
// K4: sparse correction at ct>0 pixels. atomicExch dedups overlapping windows
//     AND restores g_ct to all-zero for the next graph replay.
__global__ void k_corr(const float* __restrict__ cp) {
    int id = blockIdx.x * blockDim.x + threadIdx.x;
    float delta = 0.0f;
    int hit1 = 0;
    if (id < NB * WIN2) {
        int box = id / WIN2;
        int r   = id - box * WIN2;
        int dy  = r / WIN - RMAX;
        int dx  = (r % WIN) - RMAX;
        int rad = g_rad[box];
        if (!(dx > rad || dx < -rad || dy > rad || dy < -rad)) {
            int y = g_cyi[box] + dy;
            int x = g_cxi[box] + dx;
            if ((unsigned)y < (unsigned)Hh && (unsigned)x < (unsigned)Ww) {
                int b = box >> 6;
                int idx = ((b * Cc + g_cls[box]) * Hh + y) * Ww + x;
                int old = atomicExch((int*)&g_ct[idx], 0);
                if (old != 0) {
                    float v  = __int_as_float(old);
                    float pv = cp[idx];
                    float fb = f_bg(pv);
                    float om = 1.0f - v;
                    float om2 = om * om;
                    delta = fb * (om2 * om2 - 1.0f);
                    if (v == 1.0f) {
                        float q = 1.0f - pv;
                        delta += -__logf(pv + 1e-12f) * (q * q);
                        hit1 = 1;
                    }
                }
            }
        }
    }
    if (hit1) atomicAdd(&g_af, 1);
    float bs = block_reduce(delta);
    if (threadIdx.x == 0 && bs != 0.0f) atomicAdd(&g_acc_c, (double)bs);
}

// ---------------------------------------------------------------------------
// K5: wh/offset L1 at the <=1024 winner center pixels (CAS dedup + cleanup)
__global__ void k_wh(const float* __restrict__ wh,
                     const float* __restrict__ off) {
    int t = blockIdx.x * blockDim.x + threadIdx.x;
    if (t >= NB) return;
    int b = t >> 6, n = t & 63;
    int pix = g_cyi[t] * Ww + g_cxi[t];
    if (atomicCAS(&g_win[b * HW + pix], n + 1, 0) == n + 1) {
        const float* wp = wh  + (size_t)b * 2 * HW;
        const float* op = off + (size_t)b * 2 * HW;
        float cw = fabsf(wp[pix] - g_sw[t]) + fabsf(wp[HW + pix] - g_sh[t]);
        float co = fabsf(op[pix] - g_fx[t]) + fabsf(op[HW + pix] - g_fy[t]);
        atomicAdd(&g_acc_wh, (double)cw);
        atomicAdd(&g_acc_of, (double)co);
    }
}

// ---------------------------------------------------------------------------
__global__ void k_final(float* __restrict__ out) {
    float af = fmaxf(1.0f, (float)g_af);
    float lc = (float)g_acc_c / (af + EPS32);
    float lw = (0.1f * (float)g_acc_wh) / (af * 2.0f + EPS32);
    float lo = (float)g_acc_of / (af * 2.0f + EPS32);
    out[0] = lc + lw + lo;
}

// ---------------------------------------------------------------------------
extern "C" void kernel_launch(void* const* d_in, const int* in_sizes, int n_in,
                              void* d_out, int out_size) {
    const float* cp     = (const float*)d_in[0];   // center_pred (16,80,128,128)
    const float* wh     = (const float*)d_in[1];   // wh_pred     (16,2,128,128)
    const float* off    = (const float*)d_in[2];   // offset_pred (16,2,128,128)
    const float* boxes  = (const float*)d_in[3];   // (16,64,4)
    const int*   labels = (const int*)d_in[4];     // (16,64)
    float* out = (float*)d_out;

    k_init<<<1, NB>>>(boxes, labels);
    k_scatter<<<(NB * WIN2 + 255) / 256, 256>>>();
    k_bg<<<2048, 256>>>((const float4*)cp, TOTAL / 4);
    k_corr<<<(NB * WIN2 + 255) / 256, 256>>>(cp);
    k_wh<<<(NB + 255) / 256, 256>>>(wh, off);
    k_final<<<1, 1>>>(out);
}

// round 2
// speedup vs baseline: 1.5149x; 1.5149x over previous
#include <cuda_runtime.h>
#include <math.h>

#define Bb 16
#define Nn 64
#define Cc 80
#define Hh 128
#define Ww 128
#define HW (Hh*Ww)
#define NB (Bb*Nn)
#define RMAX 16
#define EPS32 1.1920929e-07f
#define TOTAL (Bb*Cc*HW)

#define BG_BLOCKS 2048
#define N4 (TOTAL/4)              // 5,242,880 float4
#define BLK4 (N4/BG_BLOCKS)       // 2560 float4 per bg block (exact)

// Persistent scratch. g_ct and g_win keep an "all zeros between launches"
// invariant: zero at module load, restored each launch by the consuming pass
// (atomicExch / atomicCAS cleanup).
__device__ int   g_cxi[NB], g_cyi[NB], g_rw[NB], g_cls[NB];
__device__ float g_sig2[NB], g_fx[NB], g_fy[NB], g_sw[NB], g_sh[NB];
__device__ int   g_win[Bb*HW];
__device__ float g_ct[TOTAL];
__device__ double g_acc_c, g_acc_wh, g_acc_of;
__device__ int   g_af;

// ---------------------------------------------------------------------------
__device__ __forceinline__ float block_reduce(float v) {
    __shared__ float sh[32];
    int lane = threadIdx.x & 31;
    int wid  = threadIdx.x >> 5;
    #pragma unroll
    for (int o = 16; o > 0; o >>= 1) v += __shfl_down_sync(0xffffffffu, v, o);
    if (lane == 0) sh[wid] = v;
    __syncthreads();
    int nw = (blockDim.x + 31) >> 5;
    v = (threadIdx.x < nw) ? sh[threadIdx.x] : 0.0f;
    if (wid == 0) {
        #pragma unroll
        for (int o = 16; o > 0; o >>= 1) v += __shfl_down_sync(0xffffffffu, v, o);
    }
    return v;  // valid on thread 0
}

__device__ __forceinline__ float f_bg(float p) {
    // -log(1 - p + 1e-12) * p^2
    return -__logf(1.0f - p + 1e-12f) * (p * p);
}

// ---------------------------------------------------------------------------
// Phase 1: blocks [0, NB)      -> per-box params + winner map + gaussian
//                                 scatter-max (compact window, exact size)
//          blocks [NB, NB+2048) -> dense background focal sum over 84 MB
__global__ void __launch_bounds__(256) k_phase1(const float4* __restrict__ cp4,
                                                const float*  __restrict__ boxes,
                                                const int*    __restrict__ labels) {
    int bid = blockIdx.x;
    if (bid < NB) {
        // ---- per-box scatter ----
        __shared__ int   s_cxi, s_cyi, s_rw, s_idx0;
        __shared__ float s_sig2;
        int t = bid;                       // box id = b*64 + n
        if (threadIdx.x == 0) {
            if (t == 0) { g_acc_c = 0.0; g_acc_wh = 0.0; g_acc_of = 0.0; g_af = 0; }
            float x1 = boxes[4*t+0], y1 = boxes[4*t+1];
            float x2 = boxes[4*t+2], y2 = boxes[4*t+3];
            const float wr = 0.25f, hr = 0.25f;        // W/512, H/512
            float cx = ((x1 + x2) * wr) * 0.5f;
            float cy = ((y1 + y2) * hr) * 0.5f;
            int cxi = (int)floorf(cx);
            int cyi = (int)floorf(cy);
            float sw = (x2 - x1) * wr;
            float sh = (y2 - y1) * hr;

            // gaussian radius, reference fp32 op order
            float h = sh, w = sw;
            float b1 = h + w;
            float c1 = ((w * h) * 0.7f) / 1.3f;
            float sq1 = sqrtf(b1*b1 - 4.0f*c1);
            float r1 = (b1 - sq1) * 0.5f;
            float b2 = 2.0f * (h + w);
            float c2 = (0.7f * w) * h;
            float sq2 = sqrtf(b2*b2 - 16.0f*c2);
            float r2 = (b2 - sq2) * 0.125f;
            float b3 = -0.6f * (h + w);
            float c3 = (-0.7f * w) * h;
            float sq3 = sqrtf(b3*b3 - 4.8f*c3);
            float r3 = (b3 + sq3) / 2.4f;
            float rm = fminf(fminf(r1, r2), r3);
            int rad = (int)fmaxf(0.0f, floorf(rm));

            float d = (float)(2*rad + 1);
            float sig2 = ((2.0f * d) / 6.0f) * (d / 6.0f);
            int rw = rad < RMAX ? rad : RMAX;          // effective window radius

            int b = t >> 6, n = t & 63;
            int cls = labels[t];
            g_cxi[t] = cxi; g_cyi[t] = cyi; g_rw[t] = rw; g_cls[t] = cls;
            g_sig2[t] = sig2;
            g_fx[t] = cx - (float)cxi;  g_fy[t] = cy - (float)cyi;
            g_sw[t] = sw;               g_sh[t] = sh;

            // last-wins winner: max n == last sequential writer
            atomicMax(&g_win[b * HW + cyi * Ww + cxi], n + 1);

            s_cxi = cxi; s_cyi = cyi; s_rw = rw; s_sig2 = sig2;
            s_idx0 = ((b * Cc + cls) * Hh) * Ww;
        }
        __syncthreads();
        int rw = s_rw, wdim = 2*rw + 1, nwin = wdim * wdim;
        int cxi = s_cxi, cyi = s_cyi, idx0 = s_idx0;
        float inv_s2 = 1.0f / s_sig2;
        for (int i = threadIdx.x; i < nwin; i += blockDim.x) {
            int dy = i / wdim - rw;
            int dx = i - (dy + rw) * wdim - rw;
            int y = cyi + dy, x = cxi + dx;
            if ((unsigned)y < (unsigned)Hh && (unsigned)x < (unsigned)Ww) {
                float d2   = (float)(dx*dx + dy*dy);
                float kern = expf(-d2 * inv_s2);
                if (kern >= EPS32) {
                    atomicMax((int*)&g_ct[idx0 + y * Ww + x], __float_as_int(kern));
                }
            }
        }
    } else {
        // ---- dense background focal term (memory-bound) ----
        int cb = bid - NB;
        int base = cb * BLK4;
        float s = 0.0f;
        for (int j = threadIdx.x; j < BLK4; j += blockDim.x) {
            float4 v = cp4[base + j];
            s += f_bg(v.x) + f_bg(v.y) + f_bg(v.z) + f_bg(v.w);
        }
        float bs = block_reduce(s);
        if (threadIdx.x == 0) atomicAdd(&g_acc_c, (double)bs);
    }
}

// ---------------------------------------------------------------------------
// Phase 2: one block per box. Corrects the focal loss at ct>0 pixels
// (atomicExch dedups overlaps AND re-zeroes g_ct), counts af, and thread 0
// handles the wh/offset L1 terms at winner centers (CAS dedup + cleanup).
__global__ void __launch_bounds__(256) k_phase2(const float* __restrict__ cp,
                                                const float* __restrict__ wh,
                                                const float* __restrict__ off) {
    int t = blockIdx.x;                      // box id
    int rw  = g_rw[t], wdim = 2*rw + 1, nwin = wdim * wdim;
    int cxi = g_cxi[t], cyi = g_cyi[t];
    int b = t >> 6;
    int idx0 = ((b * Cc + g_cls[t]) * Hh) * Ww;

    float delta = 0.0f;
    int hits1 = 0;
    for (int i = threadIdx.x; i < nwin; i += blockDim.x) {
        int dy = i / wdim - rw;
        int dx = i - (dy + rw) * wdim - rw;
        int y = cyi + dy, x = cxi + dx;
        if ((unsigned)y < (unsigned)Hh && (unsigned)x < (unsigned)Ww) {
            int idx = idx0 + y * Ww + x;
            int old = atomicExch((int*)&g_ct[idx], 0);
            if (old != 0) {
                float v  = __int_as_float(old);
                float pv = cp[idx];
                float fb = f_bg(pv);
                float om = 1.0f - v;
                float om2 = om * om;
                delta += fb * (om2 * om2 - 1.0f);
                if (v == 1.0f) {
                    float q = 1.0f - pv;
                    delta += -__logf(pv + 1e-12f) * (q * q);
                    hits1++;
                }
            }
        }
    }
    if (hits1) atomicAdd(&g_af, hits1);
    float bs = block_reduce(delta);
    if (threadIdx.x == 0) {
        if (bs != 0.0f) atomicAdd(&g_acc_c, (double)bs);
        // wh / offset at winner centers
        int n = t & 63;
        int pix = cyi * Ww + cxi;
        if (atomicCAS(&g_win[b * HW + pix], n + 1, 0) == n + 1) {
            const float* wp = wh  + (size_t)b * 2 * HW;
            const float* op = off + (size_t)b * 2 * HW;
            float cw = fabsf(wp[pix] - g_sw[t]) + fabsf(wp[HW + pix] - g_sh[t]);
            float co = fabsf(op[pix] - g_fx[t]) + fabsf(op[HW + pix] - g_fy[t]);
            atomicAdd(&g_acc_wh, (double)cw);
            atomicAdd(&g_acc_of, (double)co);
        }
    }
}

// ---------------------------------------------------------------------------
__global__ void k_final(float* __restrict__ out) {
    float af = fmaxf(1.0f, (float)g_af);
    float lc = (float)g_acc_c / (af + EPS32);
    float lw = (0.1f * (float)g_acc_wh) / (af * 2.0f + EPS32);
    float lo = (float)g_acc_of / (af * 2.0f + EPS32);
    out[0] = lc + lw + lo;
}

// ---------------------------------------------------------------------------
extern "C" void kernel_launch(void* const* d_in, const int* in_sizes, int n_in,
                              void* d_out, int out_size) {
    const float* cp     = (const float*)d_in[0];   // center_pred (16,80,128,128)
    const float* wh     = (const float*)d_in[1];   // wh_pred     (16,2,128,128)
    const float* off    = (const float*)d_in[2];   // offset_pred (16,2,128,128)
    const float* boxes  = (const float*)d_in[3];   // (16,64,4)
    const int*   labels = (const int*)d_in[4];     // (16,64)
    float* out = (float*)d_out;

    k_phase1<<<NB + BG_BLOCKS, 256>>>((const float4*)cp, boxes, labels);
    k_phase2<<<NB, 256>>>(cp, wh, off);
    k_final<<<1, 1>>>(out);
}